// round 17
// baseline (speedup 1.0000x reference)
#include <cuda_runtime.h>
#include <cuda_fp16.h>
#include <cuda_bf16.h>
#include <cstdint>

// int4 weight-only quantized GEMV on GB300 — cp.async pipelined version.
// Logical: A [1, K=8192], B int32 [N, K/2] (one byte per int32, two nibbles,
// low nibble = even k), scalesAndZeros [N, K/32, 2], out [1, N].
// The harness transports fp16 tensors as float32 (exact upcast, low 13
// mantissa bits zero) — detected at runtime; fp16/bf16 fallbacks kept.

#define K_DIM    8192
#define KH       (K_DIM / 2)       // 4096 int32 per row
#define KH4      (KH / 4)          // 1024 uint4 per row
#define NGROUP   (K_DIM / 32)      // 256 groups per row
#define WARPS    8
#define THREADS  (WARPS * 32)
#define ROWS     2                 // N-rows per warp
#define TILE_ROWS (WARPS * ROWS)   // 16 rows per block-tile
#define SUBS     8                 // K stages per tile
#define SUB_U4   (KH4 / SUBS)      // 128 uint4 per row per stage
#define DEPTH    4                 // cp.async pipeline depth (ring slots)

#define A_SM_BYTES (KH * 4)                            // 16 KB
#define BWARP_U4   (DEPTH * ROWS * SUB_U4)             // 1024 uint4 / warp
#define B_SM_BYTES (WARPS * BWARP_U4 * 16)             // 128 KB
#define SMEM_TOTAL (A_SM_BYTES + B_SM_BYTES)           // 144 KB

#define MODE_FP16 0
#define MODE_FP32 1
#define MODE_BF16 2

__device__ int g_mode;

// Dtype probe over the first 4096 32-bit words of A.
// FP32-from-fp16 signature: low 13 mantissa bits of every word are zero.
// fp16 vs bf16 fallback: max |halfword as fp16| (threshold 3.0 = 0x4200).
__global__ void probe_kernel(const uint32_t* __restrict__ A)
{
    __shared__ int lo13_nonzero;
    __shared__ int maxmag;
    if (threadIdx.x == 0) { lo13_nonzero = 0; maxmag = 0; }
    __syncthreads();

    int nz = 0, lmax = 0;
    for (int i = threadIdx.x; i < 4096; i += THREADS) {
        uint32_t w = A[i];
        if (w & 0x1FFFu) nz++;
        int m0 = (int)(w & 0x7FFFu);
        int m1 = (int)((w >> 16) & 0x7FFFu);
        lmax = max(lmax, max(m0, m1));
    }
    if (nz) atomicAdd(&lo13_nonzero, nz);
    atomicMax(&maxmag, lmax);
    __syncthreads();

    if (threadIdx.x == 0) {
        if (lo13_nonzero == 0)      g_mode = MODE_FP32;
        else if (maxmag > 0x4200)   g_mode = MODE_FP16;
        else                        g_mode = MODE_BF16;
    }
}

// ---- cp.async primitives ----
__device__ __forceinline__ void cp_async16(uint32_t saddr, const void* gptr) {
    asm volatile("cp.async.cg.shared.global [%0], [%1], 16;\n"
                 :: "r"(saddr), "l"(gptr));
}
__device__ __forceinline__ void cp_commit() {
    asm volatile("cp.async.commit_group;\n" ::: "memory");
}
template<int N> __device__ __forceinline__ void cp_wait() {
    asm volatile("cp.async.wait_group %0;\n" :: "n"(N) : "memory");
}

// Load one (scale, zero) pair for group g of a row, packed (half s | half z).
template<int MODE>
__device__ __forceinline__ uint32_t load_sz_packed(const void* __restrict__ SZ,
                                                   size_t row, int g)
{
    if (MODE == MODE_FP32) {
        float2 f = __ldcs(&reinterpret_cast<const float2*>(SZ)[row * NGROUP + g]);
        half2 h = __floats2half2_rn(f.x, f.y);   // exact for fp16-origin data
        return *reinterpret_cast<uint32_t*>(&h);
    } else if (MODE == MODE_BF16) {
        uint32_t w = __ldcs(&reinterpret_cast<const uint32_t*>(SZ)[row * NGROUP + g]);
        uint32_t lo = w << 16, hi = w & 0xFFFF0000u;
        half2 h = __floats2half2_rn(__uint_as_float(lo), __uint_as_float(hi));
        return *reinterpret_cast<uint32_t*>(&h);
    } else {
        return __ldcs(&reinterpret_cast<const uint32_t*>(SZ)[row * NGROUP + g]);
    }
}

// Scales for local stage L (both rows of this warp), guarded past the end.
template<int MODE>
__device__ __forceinline__ uint2 load_scales(int L, int bid, int grid, int warp,
                                             int lane, const void* __restrict__ SZ,
                                             int NTILES)
{
    uint2 r = make_uint2(0u, 0u);
    int tile = bid + (L >> 3) * grid;
    if (tile < NTILES && L >= 0) {
        int sub = L & 7;
        size_t n0 = (size_t)tile * TILE_ROWS + warp * ROWS;
        int g = sub * 32 + lane;
        r.x = load_sz_packed<MODE>(SZ, n0,     g);
        r.y = load_sz_packed<MODE>(SZ, n0 + 1, g);
    }
    return r;
}

// Issue cp.async for local stage L into this warp's ring slot. Always commits
// (possibly-empty group) so wait_group counting stays aligned at the tail.
__device__ __forceinline__ void issue_stage(int L, int bid, int grid, int warp,
                                            int lane, const int* __restrict__ B,
                                            uint32_t bwarp_saddr, int NTILES)
{
    int tile = bid + (L >> 3) * grid;
    if (tile < NTILES) {
        int sub = L & 7;
        size_t n0 = (size_t)tile * TILE_ROWS + warp * ROWS;
        int slot = L & (DEPTH - 1);
        uint32_t dst = bwarp_saddr + (uint32_t)(slot * ROWS * SUB_U4) * 16u;
        const uint4* B0 = reinterpret_cast<const uint4*>(B + n0 * KH);
        const uint4* B1 = reinterpret_cast<const uint4*>(B + (n0 + 1) * KH);
        #pragma unroll
        for (int j = 0; j < 4; ++j) {
            int gi = sub * SUB_U4 + j * 32 + lane;
            cp_async16(dst + (uint32_t)(j * 32 + lane) * 16u,            &B0[gi]);
            cp_async16(dst + (uint32_t)(SUB_U4 + j * 32 + lane) * 16u,   &B1[gi]);
        }
    }
    cp_commit();
}

// 4 half2 dequant+dot chain for one uint4 (8 weights), flushed to fp32.
__device__ __forceinline__ void dot_u4(uint4 bv, uint4 av, half2 s2, half2 z2,
                                       half2 c1032, float2& facc)
{
    uint32_t v, hb; half2 h2, d2, w2, a2, acc2;

    v = (uint32_t)bv.x;
    hb = ((v & 0xFu) | 0x64006400u) | ((v << 12) & 0x000F0000u);
    h2 = *reinterpret_cast<half2*>(&hb);
    d2 = __hsub2(h2, c1032);                 // exact (q - 8), Sterbenz
    w2 = __hfma2(d2, s2, z2);
    a2 = *reinterpret_cast<half2*>(&av.x);
    acc2 = __hmul2(a2, w2);

    v = (uint32_t)bv.y;
    hb = ((v & 0xFu) | 0x64006400u) | ((v << 12) & 0x000F0000u);
    h2 = *reinterpret_cast<half2*>(&hb);
    d2 = __hsub2(h2, c1032);
    w2 = __hfma2(d2, s2, z2);
    a2 = *reinterpret_cast<half2*>(&av.y);
    acc2 = __hfma2(a2, w2, acc2);

    v = (uint32_t)bv.z;
    hb = ((v & 0xFu) | 0x64006400u) | ((v << 12) & 0x000F0000u);
    h2 = *reinterpret_cast<half2*>(&hb);
    d2 = __hsub2(h2, c1032);
    w2 = __hfma2(d2, s2, z2);
    a2 = *reinterpret_cast<half2*>(&av.z);
    acc2 = __hfma2(a2, w2, acc2);

    v = (uint32_t)bv.w;
    hb = ((v & 0xFu) | 0x64006400u) | ((v << 12) & 0x000F0000u);
    h2 = *reinterpret_cast<half2*>(&hb);
    d2 = __hsub2(h2, c1032);
    w2 = __hfma2(d2, s2, z2);
    a2 = *reinterpret_cast<half2*>(&av.w);
    acc2 = __hfma2(a2, w2, acc2);

    float2 f = __half22float2(acc2);
    facc.x += f.x;
    facc.y += f.y;
}

template<int MODE>
__device__ __forceinline__ void run(const int* __restrict__ B,
                                    const void* __restrict__ SZ,
                                    void* __restrict__ outp, int N,
                                    const uint4* __restrict__ As4,
                                    const uint4* __restrict__ bwarp,
                                    uint32_t bwarp_saddr,
                                    int lane, int warp, int bid, int grid)
{
    const int NTILES = N / TILE_ROWS;
    const int nt_b   = (bid < NTILES) ? ((NTILES - bid + grid - 1) / grid) : 0;
    const int totalL = nt_b * SUBS;
    if (totalL == 0) return;

    const half2 c1032 = __half2half2(__ushort_as_half(0x6408));  // 1032.0

    // prologue: fill the ring
    #pragma unroll
    for (int L = 0; L < DEPTH; ++L)
        issue_stage(L, bid, grid, warp, lane, B, bwarp_saddr, NTILES);

    uint2 s_cur = load_scales<MODE>(0, bid, grid, warp, lane, SZ, NTILES);
    uint2 s_n1  = load_scales<MODE>(1, bid, grid, warp, lane, SZ, NTILES);

    float2 facc0 = make_float2(0.f, 0.f);
    float2 facc1 = make_float2(0.f, 0.f);

    for (int L = 0; L < totalL; ++L) {
        cp_wait<DEPTH - 1>();                     // stage L resident in smem

        uint2 s_n2 = load_scales<MODE>(L + 2, bid, grid, warp, lane, SZ, NTILES);

        const int sub  = L & 7;
        const int slot = L & (DEPTH - 1);
        const uint4* bs = bwarp + slot * ROWS * SUB_U4;

        #pragma unroll
        for (int j = 0; j < 4; ++j) {
            uint4 av = As4[sub * SUB_U4 + j * 32 + lane];   // conflict-free
            const int src = j * 8 + (lane >> 2);            // group owner lane
            uint32_t p0 = __shfl_sync(0xFFFFFFFFu, s_cur.x, src);
            uint32_t p1 = __shfl_sync(0xFFFFFFFFu, s_cur.y, src);
            uint4 bv0 = bs[j * 32 + lane];
            uint4 bv1 = bs[SUB_U4 + j * 32 + lane];

            half2 h0 = *reinterpret_cast<half2*>(&p0);
            dot_u4(bv0, av, __half2half2(__low2half(h0)),
                   __half2half2(__high2half(h0)), c1032, facc0);
            half2 h1 = *reinterpret_cast<half2*>(&p1);
            dot_u4(bv1, av, __half2half2(__low2half(h1)),
                   __half2half2(__high2half(h1)), c1032, facc1);
        }

        // refill the slot just consumed (stage L+DEPTH); safe: same warp,
        // LDS reads above are ~29cyc deep while the async write lands >=234cyc
        // after issue.
        issue_stage(L + DEPTH, bid, grid, warp, lane, B, bwarp_saddr, NTILES);

        s_cur = s_n1; s_n1 = s_n2;

        if (sub == 7) {                          // end of tile: reduce + store
            int tile = bid + (L >> 3) * grid;
            size_t n0 = (size_t)tile * TILE_ROWS + warp * ROWS;
            float r0 = facc0.x + facc0.y;
            float r1 = facc1.x + facc1.y;
            #pragma unroll
            for (int off = 16; off > 0; off >>= 1) {
                r0 += __shfl_xor_sync(0xFFFFFFFFu, r0, off);
                r1 += __shfl_xor_sync(0xFFFFFFFFu, r1, off);
            }
            if (lane == 0) {
                if (MODE == MODE_FP32) {
                    reinterpret_cast<float*>(outp)[n0]     = r0;
                    reinterpret_cast<float*>(outp)[n0 + 1] = r1;
                } else if (MODE == MODE_BF16) {
                    reinterpret_cast<__nv_bfloat16*>(outp)[n0]     = __float2bfloat16(r0);
                    reinterpret_cast<__nv_bfloat16*>(outp)[n0 + 1] = __float2bfloat16(r1);
                } else {
                    reinterpret_cast<__half*>(outp)[n0]     = __float2half(r0);
                    reinterpret_cast<__half*>(outp)[n0 + 1] = __float2half(r1);
                }
            }
            facc0 = make_float2(0.f, 0.f);
            facc1 = make_float2(0.f, 0.f);
        }
    }
}

__global__ __launch_bounds__(THREADS)
void gemv_int4_kernel(const void* __restrict__ Aptr,
                      const int*  __restrict__ B,
                      const void* __restrict__ SZptr,
                      void*       __restrict__ outptr,
                      int N)
{
    extern __shared__ __align__(16) char smem[];
    uint32_t* a_sm = reinterpret_cast<uint32_t*>(smem);              // 16 KB
    uint4*    bsm  = reinterpret_cast<uint4*>(smem + A_SM_BYTES);    // 128 KB ring

    const int mode = g_mode;

    // Stage A once per block as packed half2 pairs (exact conversions).
    if (mode == MODE_FP32) {
        const float2* Av = reinterpret_cast<const float2*>(Aptr);
        for (int i = threadIdx.x; i < KH; i += THREADS) {
            float2 v = Av[i];
            half2 h = __floats2half2_rn(v.x, v.y);
            a_sm[i] = *reinterpret_cast<uint32_t*>(&h);
        }
    } else if (mode == MODE_BF16) {
        const uint32_t* Av = reinterpret_cast<const uint32_t*>(Aptr);
        for (int i = threadIdx.x; i < KH; i += THREADS) {
            uint32_t w = Av[i];
            uint32_t lo = w << 16, hi = w & 0xFFFF0000u;
            half2 h = __floats2half2_rn(__uint_as_float(lo), __uint_as_float(hi));
            a_sm[i] = *reinterpret_cast<uint32_t*>(&h);
        }
    } else {
        const uint32_t* Av = reinterpret_cast<const uint32_t*>(Aptr);
        for (int i = threadIdx.x; i < KH; i += THREADS)
            a_sm[i] = Av[i];
    }
    __syncthreads();

    const int warp = threadIdx.x >> 5;
    const int lane = threadIdx.x & 31;

    const uint4* As4   = reinterpret_cast<const uint4*>(a_sm);
    const uint4* bwarp = bsm + warp * BWARP_U4;
    uint32_t bwarp_saddr =
        (uint32_t)__cvta_generic_to_shared(bsm) + (uint32_t)(warp * BWARP_U4) * 16u;

    if (mode == MODE_FP32)
        run<MODE_FP32>(B, SZptr, outptr, N, As4, bwarp, bwarp_saddr,
                       lane, warp, blockIdx.x, gridDim.x);
    else if (mode == MODE_BF16)
        run<MODE_BF16>(B, SZptr, outptr, N, As4, bwarp, bwarp_saddr,
                       lane, warp, blockIdx.x, gridDim.x);
    else
        run<MODE_FP16>(B, SZptr, outptr, N, As4, bwarp, bwarp_saddr,
                       lane, warp, blockIdx.x, gridDim.x);
}

extern "C" void kernel_launch(void* const* d_in, const int* in_sizes, int n_in,
                              void* d_out, int out_size)
{
    // Identify tensors by element count (ordering-proof):
    //   A = 8192, B = N*K/2 (largest), SZ = N*K/32*2
    int iA = -1, iB = -1, iS = -1;
    for (int i = 0; i < n_in; ++i) {
        if      (in_sizes[i] == K_DIM) iA = i;
        else if (iB < 0 || in_sizes[i] > in_sizes[iB]) { if (iB >= 0) iS = iB; iB = i; }
        else iS = i;
    }
    if (iA < 0 || iB < 0 || iS < 0) { iA = 0; iB = 1; iS = 2; }

    const void* A  = d_in[iA];
    const int*  B  = (const int*)d_in[iB];
    const void* SZ = d_in[iS];

    const int N = in_sizes[iB] / KH;

    int dev = 0, sms = 148;
    cudaGetDevice(&dev);
    cudaDeviceGetAttribute(&sms, cudaDevAttrMultiProcessorCount, dev);

    cudaFuncSetAttribute(gemv_int4_kernel,
                         cudaFuncAttributeMaxDynamicSharedMemorySize, SMEM_TOTAL);

    probe_kernel<<<1, THREADS>>>((const uint32_t*)A);
    gemv_int4_kernel<<<sms, THREADS, SMEM_TOTAL>>>(A, B, SZ, d_out, N);
}